// round 5
// baseline (speedup 1.0000x reference)
#include <cuda_runtime.h>
#include <cuda_bf16.h>
#include <math.h>

// Problem constants
#define BATCH   8192
#define DIM     1024      // DIM1 == DIM2
#define SKETCH  8192
#define OUT     512
#define LN_EPS  1e-5f

#define MCAP    1024      // |J| <= 1024
#define CCH     128       // column chunk for main kernel
#define TB      32        // batch rows per CTA in main kernel
#define NTHR    512       // threads per CTA in main kernel

// ---------------- device globals (scratch; no cudaMalloc allowed) ----------
__device__ unsigned int g_idx1[DIM];     // per input dim: (signbit<<31) | bucket
__device__ unsigned int g_idx2[DIM];
__device__ int          g_m;             // |J|
__device__ int          g_colJ[MCAP];    // compact c -> original column j
__device__ int          g_cp1[MCAP + 1]; // CSR col ptrs, side 1
__device__ int          g_cp2[MCAP + 1];
__device__ unsigned int g_ent1[MCAP];    // CSR entries: (sign<<15) | i
__device__ unsigned int g_ent2[MCAP];
__device__ float        g_Wc2[MCAP * OUT * 2]; // compacted W rows, DUPLICATED pairs

// -------- f32x2 packed-FMA helpers (PTX-only; ptxas never emits these) -----
__device__ __forceinline__ unsigned long long pack2(float lo, float hi) {
    unsigned long long r;
    asm("mov.b64 %0, {%1, %2};" : "=l"(r) : "f"(lo), "f"(hi));
    return r;
}
__device__ __forceinline__ void unpack2(unsigned long long v, float& lo, float& hi) {
    asm("mov.b64 {%0, %1}, %2;" : "=f"(lo), "=f"(hi) : "l"(v));
}
__device__ __forceinline__ unsigned long long ffma2(unsigned long long a,
                                                    unsigned long long b,
                                                    unsigned long long c) {
    unsigned long long d;
    asm("fma.rn.f32x2 %0, %1, %2, %3;" : "=l"(d) : "l"(a), "l"(b), "l"(c));
    return d;
}

// ---------------------------------------------------------------------------
// Kernel A: find the single nonzero per row of S1/S2. Coalesced float4 scan.
// ---------------------------------------------------------------------------
__global__ void k_extract(const float* __restrict__ S1,
                          const float* __restrict__ S2)
{
    int row = blockIdx.x;
    const float* S;
    unsigned int* outp;
    if (row < DIM) { S = S1; outp = g_idx1; }
    else           { S = S2; outp = g_idx2; row -= DIM; }

    const float4* p = (const float4*)(S + (size_t)row * SKETCH);
    int t = threadIdx.x;
#pragma unroll
    for (int k = 0; k < SKETCH / 4 / 256; k++) {
        int v4 = t + k * 256;
        float4 v = p[v4];
        int base = v4 * 4;
        if (v.x != 0.0f) outp[row] = (unsigned)(base + 0) | (v.x < 0.0f ? 0x80000000u : 0u);
        if (v.y != 0.0f) outp[row] = (unsigned)(base + 1) | (v.y < 0.0f ? 0x80000000u : 0u);
        if (v.z != 0.0f) outp[row] = (unsigned)(base + 2) | (v.z < 0.0f ? 0x80000000u : 0u);
        if (v.w != 0.0f) outp[row] = (unsigned)(base + 3) | (v.w < 0.0f ? 0x80000000u : 0u);
    }
}

// ---------------------------------------------------------------------------
// Kernel B: build compact structure + per-column CSR. One CTA, 1024 threads.
// ---------------------------------------------------------------------------
__global__ void k_build()
{
    __shared__ int cnt[SKETCH];      // packed occupancy counts, then colmap
    __shared__ int scanbuf[1024];
    __shared__ int colcnt[MCAP];     // per-column entry counts / running offsets

    int t = threadIdx.x;

    for (int j = t; j < SKETCH; j += 1024) cnt[j] = 0;
    __syncthreads();

    unsigned u1 = g_idx1[t];
    unsigned u2 = g_idx2[t];
    atomicAdd(&cnt[u1 & (SKETCH - 1)], 1);
    atomicAdd(&cnt[u2 & (SKETCH - 1)], 1 << 16);
    __syncthreads();

    // qualification + prefix scan: thread t owns j in [t*8, t*8+8)
    int q = 0;
    int qual[8];
#pragma unroll
    for (int u = 0; u < 8; u++) {
        int j = t * 8 + u;
        int c = cnt[j];
        qual[u] = ((c & 0xFFFF) > 0 && (c >> 16) > 0) ? 1 : 0;
        q += qual[u];
    }
    scanbuf[t] = q;
    __syncthreads();
    for (int off = 1; off < 1024; off <<= 1) {
        int v = (t >= off) ? scanbuf[t - off] : 0;
        __syncthreads();
        scanbuf[t] += v;
        __syncthreads();
    }
    int excl = scanbuf[t] - q;
    int total = scanbuf[1023];

#pragma unroll
    for (int u = 0; u < 8; u++) {
        int j = t * 8 + u;
        if (qual[u]) { g_colJ[excl] = j; cnt[j] = excl; excl++; }
        else         { cnt[j] = -1; }
    }
    if (t == 0) g_m = total;
    __syncthreads();

    // CSR build for both sides
    int c1 = cnt[u1 & (SKETCH - 1)];
    int c2 = cnt[u2 & (SKETCH - 1)];
#pragma unroll
    for (int s = 0; s < 2; s++) {
        int cc = s ? c2 : c1;
        unsigned uu = s ? u2 : u1;
        int* cp = s ? g_cp2 : g_cp1;
        unsigned int* ent = s ? g_ent2 : g_ent1;

        colcnt[t] = 0;
        __syncthreads();
        if (cc >= 0) atomicAdd(&colcnt[cc], 1);
        __syncthreads();

        int myc = colcnt[t];
        scanbuf[t] = myc;
        __syncthreads();
        for (int off = 1; off < 1024; off <<= 1) {
            int v = (t >= off) ? scanbuf[t - off] : 0;
            __syncthreads();
            scanbuf[t] += v;
            __syncthreads();
        }
        int ex = scanbuf[t] - myc;
        cp[t] = ex;
        if (t == 1023) cp[1024] = scanbuf[1023];
        colcnt[t] = ex;      // running offsets
        __syncthreads();
        if (cc >= 0) {
            int slot = atomicAdd(&colcnt[cc], 1);
            ent[slot] = (((uu >> 31) & 1u) << 15) | (unsigned)t;
        }
        __syncthreads();
    }
}

// ---------------------------------------------------------------------------
// Kernel B2: gather compacted W rows, duplicating each value into a b64 pair
// so the main GEMM can LDG the f32x2 multiplier directly (no pack MOVs).
// ---------------------------------------------------------------------------
__global__ void k_wgather(const float* __restrict__ W)
{
    int c = blockIdx.x;
    if (c < g_m) {
        float v = W[(size_t)g_colJ[c] * OUT + threadIdx.x];
        float2* dst = (float2*)&g_Wc2[((size_t)c * OUT + threadIdx.x) * 2];
        *dst = make_float2(v, v);
    }
}

// ---------------------------------------------------------------------------
// Main fused kernel. TB=32 rows/CTA, 512 threads, 256 CTAs.
//  Thread layout: tc = tid&63 (8 output cols each), rg = tid>>6 (4 rows each).
//  Phase 1: CSR gather — v[c][r] = s1(c,r)*s2(c,r), no atomics.
//  Phase 2: register GEMM, packed fma.rn.f32x2; v row-pairs come packed from
//           smem (LDS.128), W comes pre-duplicated from g_Wc2 (LDG.128).
//  Epilogue: LayerNorm (bias folded into acc init) + ReLU.
// ---------------------------------------------------------------------------
__global__ void __launch_bounds__(NTHR, 2)
k_main(const float* __restrict__ x1, const float* __restrict__ x2,
       const float* __restrict__ bias, const float* __restrict__ gamma,
       const float* __restrict__ beta, float* __restrict__ out)
{
    __shared__ float s1c[CCH * TB];          // product tile [Cn][TB]; LN buffer
    __shared__ int sh_cp1[MCAP + 1], sh_cp2[MCAP + 1];
    __shared__ unsigned int sh_e1[MCAP], sh_e2[MCAP];
    __shared__ float sh_mu[TB], sh_rs[TB];

    int tid = threadIdx.x;
    int b0  = blockIdx.x * TB;
    int tc  = tid & 63;          // output-column group (64 groups x 8 cols)
    int o0  = tc * 8;
    int r0  = (tid >> 6) * 4;    // row group base (0,4,...,28)

    int m = g_m;                 // L2 broadcast
    for (int i = tid; i <= m; i += NTHR) {
        sh_cp1[i] = g_cp1[i];
        sh_cp2[i] = g_cp2[i];
    }
    for (int i = tid; i < m + 32 && i < MCAP; i += NTHR) {
        sh_e1[i] = g_ent1[i];
        sh_e2[i] = g_ent2[i];
    }
    __syncthreads();

    int nch = (m + CCH - 1) / CCH;

    // accumulators: acc2[jp][k] = rows (r0+2jp, r0+2jp+1) packed, col o0+k
    unsigned long long acc2[2][8];
    {
        float4 ba = *(const float4*)(bias + o0);
        float4 bb = *(const float4*)(bias + o0 + 4);
        float bi[8] = {ba.x, ba.y, ba.z, ba.w, bb.x, bb.y, bb.z, bb.w};
#pragma unroll
        for (int k = 0; k < 8; k++) {
            unsigned long long b2 = pack2(bi[k], bi[k]);
            acc2[0][k] = b2;
            acc2[1][k] = b2;
        }
    }

    for (int ch = 0; ch < nch; ch++) {
        int ck0 = ch * CCH;
        int Cn  = min(CCH, m - ck0);

        // ---- gather: v[c][r] = s1(c,r) * s2(c,r), no atomics ----
        {
            int nw = Cn * TB;
#pragma unroll 2
            for (int p = tid; p < nw; p += NTHR) {
                int cl = p >> 5;
                int r  = p & 31;
                int c  = ck0 + cl;
                size_t rowoff = (size_t)(b0 + r) * DIM;

                float s1 = 0.0f;
                int e0 = sh_cp1[c], e1 = sh_cp1[c + 1];
                for (int e = e0; e < e1; e++) {
                    unsigned u = sh_e1[e];
                    float x = __ldg(&x1[rowoff + (u & 1023u)]);
                    s1 += (u & 0x8000u) ? -x : x;
                }
                float s2 = 0.0f;
                int f0 = sh_cp2[c], f1 = sh_cp2[c + 1];
                for (int e = f0; e < f1; e++) {
                    unsigned u = sh_e2[e];
                    float x = __ldg(&x2[rowoff + (u & 1023u)]);
                    s2 += (u & 0x8000u) ? -x : x;
                }
                s1c[cl * TB + r] = s1 * s2;
            }
        }
        __syncthreads();

        // ---- GEMM: acc += v[32 x Cn] @ Wc[Cn x 512], packed f32x2 ----
        const unsigned long long* Wp =
            (const unsigned long long*)g_Wc2 + ((size_t)ck0 * OUT + o0);
#pragma unroll 2
        for (int cl = 0; cl < Cn; cl++) {
            // 4 rows packed as 2 b64 values, direct from smem
            const ulonglong2* vp = (const ulonglong2*)&s1c[cl * TB + r0];
            ulonglong2 va = vp[0];
            unsigned long long v0 = va.x, v1 = va.y;

            // 8 pre-duplicated W pairs: 4 x LDG.128 (L1-resident)
            const ulonglong2* wq = (const ulonglong2*)(Wp + (size_t)cl * OUT);
            ulonglong2 w01 = __ldg(wq + 0);
            ulonglong2 w23 = __ldg(wq + 1);
            ulonglong2 w45 = __ldg(wq + 2);
            ulonglong2 w67 = __ldg(wq + 3);
            unsigned long long ww[8] = {w01.x, w01.y, w23.x, w23.y,
                                        w45.x, w45.y, w67.x, w67.y};
#pragma unroll
            for (int k = 0; k < 8; k++) {
                acc2[0][k] = ffma2(v0, ww[k], acc2[0][k]);
                acc2[1][k] = ffma2(v1, ww[k], acc2[1][k]);
            }
        }
        __syncthreads();   // s1c rewritten next chunk (or reused by LN)
    }

    // -------- LayerNorm reduction across the 64 column-group threads -------
    float* red_s = s1c;              // [TB][64]
    float* red_q = s1c + TB * 64;
#pragma unroll
    for (int jp = 0; jp < 2; jp++) {
        float slo = 0.0f, qlo = 0.0f, shi = 0.0f, qhi = 0.0f;
#pragma unroll
        for (int k = 0; k < 8; k++) {
            float lo, hi;
            unpack2(acc2[jp][k], lo, hi);
            slo += lo; qlo += lo * lo;
            shi += hi; qhi += hi * hi;
        }
        int rlo = r0 + 2 * jp, rhi = rlo + 1;
        red_s[rlo * 64 + tc] = slo;
        red_q[rlo * 64 + tc] = qlo;
        red_s[rhi * 64 + tc] = shi;
        red_q[rhi * 64 + tc] = qhi;
    }
    __syncthreads();
    if (tid < TB) {
        float s = 0.0f, q = 0.0f;
        for (int u = 0; u < 64; u++) {
            int u2 = (u + tid) & 63;            // skew to avoid bank conflicts
            s += red_s[tid * 64 + u2];
            q += red_q[tid * 64 + u2];
        }
        float mu  = s * (1.0f / OUT);
        float var = q * (1.0f / OUT) - mu * mu;
        sh_mu[tid] = mu;
        sh_rs[tid] = rsqrtf(var + LN_EPS);
    }
    __syncthreads();

    // -------- normalize, affine, ReLU, store -------------------------------
    float4 ga4 = *(const float4*)(gamma + o0);
    float4 gb4 = *(const float4*)(gamma + o0 + 4);
    float4 ba4 = *(const float4*)(beta + o0);
    float4 bb4 = *(const float4*)(beta + o0 + 4);
    float ga[8] = {ga4.x, ga4.y, ga4.z, ga4.w, gb4.x, gb4.y, gb4.z, gb4.w};
    float be[8] = {ba4.x, ba4.y, ba4.z, ba4.w, bb4.x, bb4.y, bb4.z, bb4.w};

#pragma unroll
    for (int jp = 0; jp < 2; jp++) {
        int rlo = r0 + 2 * jp;
        float mulo = sh_mu[rlo],     rslo = sh_rs[rlo];
        float muhi = sh_mu[rlo + 1], rshi = sh_rs[rlo + 1];
        float olo[8], ohi[8];
#pragma unroll
        for (int k = 0; k < 8; k++) {
            float lo, hi;
            unpack2(acc2[jp][k], lo, hi);
            olo[k] = fmaxf((lo - mulo) * rslo * ga[k] + be[k], 0.0f);
            ohi[k] = fmaxf((hi - muhi) * rshi * ga[k] + be[k], 0.0f);
        }
        float* dlo = out + (size_t)(b0 + rlo) * OUT + o0;
        float* dhi = out + (size_t)(b0 + rlo + 1) * OUT + o0;
        *(float4*)(dlo)     = make_float4(olo[0], olo[1], olo[2], olo[3]);
        *(float4*)(dlo + 4) = make_float4(olo[4], olo[5], olo[6], olo[7]);
        *(float4*)(dhi)     = make_float4(ohi[0], ohi[1], ohi[2], ohi[3]);
        *(float4*)(dhi + 4) = make_float4(ohi[4], ohi[5], ohi[6], ohi[7]);
    }
}

// ---------------------------------------------------------------------------
extern "C" void kernel_launch(void* const* d_in, const int* in_sizes, int n_in,
                              void* d_out, int out_size)
{
    const float* x1    = (const float*)d_in[0];
    const float* x2    = (const float*)d_in[1];
    const float* S1    = (const float*)d_in[2];
    const float* S2    = (const float*)d_in[3];
    const float* W     = (const float*)d_in[4];
    const float* b     = (const float*)d_in[5];
    const float* gamma = (const float*)d_in[6];
    const float* beta  = (const float*)d_in[7];
    float* out = (float*)d_out;

    k_extract<<<2 * DIM, 256>>>(S1, S2);
    k_build<<<1, 1024>>>();
    k_wgather<<<MCAP, OUT>>>(W);
    k_main<<<BATCH / TB, NTHR>>>(x1, x2, b, gamma, beta, out);
}

// round 6
// speedup vs baseline: 1.4586x; 1.4586x over previous
#include <cuda_runtime.h>
#include <cuda_bf16.h>
#include <math.h>

// Problem constants
#define BATCH   8192
#define DIM     1024      // DIM1 == DIM2
#define SKETCH  8192
#define OUT     512
#define LN_EPS  1e-5f

#define MCAP    1024      // |J| <= 1024
#define CCH     128       // column chunk for main kernel
#define TB      32        // batch rows per CTA in main kernel
#define NTHR    512       // threads per CTA in main kernel (16 warps)

// ---------------- device globals (scratch; no cudaMalloc allowed) ----------
__device__ unsigned int g_idx1[DIM];     // per input dim: (signbit<<31) | bucket
__device__ unsigned int g_idx2[DIM];
__device__ int          g_m;             // |J|
__device__ int          g_colJ[MCAP];    // compact c -> original column j
__device__ int          g_cp1[MCAP + 1]; // CSR col ptrs, side 1
__device__ int          g_cp2[MCAP + 1];
__device__ unsigned int g_ent1[MCAP];    // CSR entries: (sign<<15) | i
__device__ unsigned int g_ent2[MCAP];
__device__ float        g_Wc[MCAP * OUT]; // compacted W rows (NOT duplicated)

// -------- f32x2 packed-FMA helpers (PTX-only; ptxas never emits these) -----
__device__ __forceinline__ unsigned long long pack2(float lo, float hi) {
    unsigned long long r;
    asm("mov.b64 %0, {%1, %2};" : "=l"(r) : "f"(lo), "f"(hi));
    return r;
}
__device__ __forceinline__ void unpack2(unsigned long long v, float& lo, float& hi) {
    asm("mov.b64 {%0, %1}, %2;" : "=f"(lo), "=f"(hi) : "l"(v));
}
__device__ __forceinline__ unsigned long long ffma2(unsigned long long a,
                                                    unsigned long long b,
                                                    unsigned long long c) {
    unsigned long long d;
    asm("fma.rn.f32x2 %0, %1, %2, %3;" : "=l"(d) : "l"(a), "l"(b), "l"(c));
    return d;
}

// ---------------------------------------------------------------------------
// Kernel A: find the single nonzero per row of S1/S2. Coalesced float4 scan.
// ---------------------------------------------------------------------------
__global__ void k_extract(const float* __restrict__ S1,
                          const float* __restrict__ S2)
{
    int row = blockIdx.x;
    const float* S;
    unsigned int* outp;
    if (row < DIM) { S = S1; outp = g_idx1; }
    else           { S = S2; outp = g_idx2; row -= DIM; }

    const float4* p = (const float4*)(S + (size_t)row * SKETCH);
    int t = threadIdx.x;
#pragma unroll
    for (int k = 0; k < SKETCH / 4 / 256; k++) {
        int v4 = t + k * 256;
        float4 v = p[v4];
        int base = v4 * 4;
        if (v.x != 0.0f) outp[row] = (unsigned)(base + 0) | (v.x < 0.0f ? 0x80000000u : 0u);
        if (v.y != 0.0f) outp[row] = (unsigned)(base + 1) | (v.y < 0.0f ? 0x80000000u : 0u);
        if (v.z != 0.0f) outp[row] = (unsigned)(base + 2) | (v.z < 0.0f ? 0x80000000u : 0u);
        if (v.w != 0.0f) outp[row] = (unsigned)(base + 3) | (v.w < 0.0f ? 0x80000000u : 0u);
    }
}

// ---------------------------------------------------------------------------
// Kernel B: build compact structure + per-column CSR. One CTA, 1024 threads.
// ---------------------------------------------------------------------------
__global__ void k_build()
{
    __shared__ int cnt[SKETCH];      // packed occupancy counts, then colmap
    __shared__ int scanbuf[1024];
    __shared__ int colcnt[MCAP];     // per-column entry counts / running offsets

    int t = threadIdx.x;

    for (int j = t; j < SKETCH; j += 1024) cnt[j] = 0;
    __syncthreads();

    unsigned u1 = g_idx1[t];
    unsigned u2 = g_idx2[t];
    atomicAdd(&cnt[u1 & (SKETCH - 1)], 1);
    atomicAdd(&cnt[u2 & (SKETCH - 1)], 1 << 16);
    __syncthreads();

    // qualification + prefix scan: thread t owns j in [t*8, t*8+8)
    int q = 0;
    int qual[8];
#pragma unroll
    for (int u = 0; u < 8; u++) {
        int j = t * 8 + u;
        int c = cnt[j];
        qual[u] = ((c & 0xFFFF) > 0 && (c >> 16) > 0) ? 1 : 0;
        q += qual[u];
    }
    scanbuf[t] = q;
    __syncthreads();
    for (int off = 1; off < 1024; off <<= 1) {
        int v = (t >= off) ? scanbuf[t - off] : 0;
        __syncthreads();
        scanbuf[t] += v;
        __syncthreads();
    }
    int excl = scanbuf[t] - q;
    int total = scanbuf[1023];

#pragma unroll
    for (int u = 0; u < 8; u++) {
        int j = t * 8 + u;
        if (qual[u]) { g_colJ[excl] = j; cnt[j] = excl; excl++; }
        else         { cnt[j] = -1; }
    }
    if (t == 0) g_m = total;
    __syncthreads();

    // CSR build for both sides
    int c1 = cnt[u1 & (SKETCH - 1)];
    int c2 = cnt[u2 & (SKETCH - 1)];
#pragma unroll
    for (int s = 0; s < 2; s++) {
        int cc = s ? c2 : c1;
        unsigned uu = s ? u2 : u1;
        int* cp = s ? g_cp2 : g_cp1;
        unsigned int* ent = s ? g_ent2 : g_ent1;

        colcnt[t] = 0;
        __syncthreads();
        if (cc >= 0) atomicAdd(&colcnt[cc], 1);
        __syncthreads();

        int myc = colcnt[t];
        scanbuf[t] = myc;
        __syncthreads();
        for (int off = 1; off < 1024; off <<= 1) {
            int v = (t >= off) ? scanbuf[t - off] : 0;
            __syncthreads();
            scanbuf[t] += v;
            __syncthreads();
        }
        int ex = scanbuf[t] - myc;
        cp[t] = ex;
        if (t == 1023) cp[1024] = scanbuf[1023];
        colcnt[t] = ex;      // running offsets
        __syncthreads();
        if (cc >= 0) {
            int slot = atomicAdd(&colcnt[cc], 1);
            ent[slot] = (((uu >> 31) & 1u) << 15) | (unsigned)t;
        }
        __syncthreads();
    }
}

// ---------------------------------------------------------------------------
// Kernel B2: gather compacted W rows (plain copy; f32x2 pairs are now
// adjacent COLUMNS, so no duplication is needed).
// ---------------------------------------------------------------------------
__global__ void k_wgather(const float* __restrict__ W)
{
    int c = blockIdx.x;
    if (c < g_m) {
        g_Wc[(size_t)c * OUT + threadIdx.x] =
            W[(size_t)g_colJ[c] * OUT + threadIdx.x];
    }
}

// ---------------------------------------------------------------------------
// Main fused kernel. TB=32 rows/CTA, 512 threads (16 warps), 256 CTAs.
//  GEMM mapping: lane = row (32 rows), warp = 32 output cols (16x32=512).
//   -> W loads are warp-UNIFORM (broadcast, 1 wavefront each); f32x2 packs
//      two adjacent columns; v is one conflict-free LDS.32 + pack2 per cl.
//  Phase 1: CSR gather — v[c][r] = s1(c,r)*s2(c,r), no atomics.
//  Epilogue: LayerNorm (bias folded into acc init) + ReLU.
// ---------------------------------------------------------------------------
__global__ void __launch_bounds__(NTHR, 2)
k_main(const float* __restrict__ x1, const float* __restrict__ x2,
       const float* __restrict__ bias, const float* __restrict__ gamma,
       const float* __restrict__ beta, float* __restrict__ out)
{
    __shared__ float s1c[CCH * TB];          // product tile [Cn][TB]
    __shared__ int sh_cp1[MCAP + 1], sh_cp2[MCAP + 1];
    __shared__ unsigned int sh_e1[MCAP], sh_e2[MCAP];
    __shared__ float red_s[TB * 17], red_q[TB * 17];   // padded LN buffers
    __shared__ float sh_mu[TB], sh_rs[TB];

    int tid  = threadIdx.x;
    int lane = tid & 31;          // row within tile
    int wrp  = tid >> 5;          // 0..15 -> cols [wrp*32, wrp*32+32)
    int o0   = wrp * 32;
    int b0   = blockIdx.x * TB;

    int m = g_m;                  // L2 broadcast
    for (int i = tid; i <= m; i += NTHR) {
        sh_cp1[i] = g_cp1[i];
        sh_cp2[i] = g_cp2[i];
    }
    for (int i = tid; i < m + 32 && i < MCAP; i += NTHR) {
        sh_e1[i] = g_ent1[i];
        sh_e2[i] = g_ent2[i];
    }
    __syncthreads();

    int nch = (m + CCH - 1) / CCH;

    // accumulators: acc2[k] = cols (o0+2k, o0+2k+1) for row `lane`
    unsigned long long acc2[16];
    {
        const ulonglong2* bp = (const ulonglong2*)(bias + o0);
#pragma unroll
        for (int q = 0; q < 4; q++) {
            ulonglong2 b = bp[q];
            acc2[q * 4 + 0] = b.x;   // wait—this is wrong granularity; see below
            acc2[q * 4 + 1] = b.y;
            acc2[q * 4 + 2] = 0;     // placeholder, overwritten just after
            acc2[q * 4 + 3] = 0;
        }
        // proper init: 8 x ulonglong2 = 16 pairs
        const ulonglong2* bq = (const ulonglong2*)(bias + o0);
#pragma unroll
        for (int q = 0; q < 8; q++) {
            ulonglong2 b = bq[q];
            acc2[q * 2 + 0] = b.x;
            acc2[q * 2 + 1] = b.y;
        }
    }

    for (int ch = 0; ch < nch; ch++) {
        int ck0 = ch * CCH;
        int Cn  = min(CCH, m - ck0);

        // ---- gather: v[c][r] = s1(c,r) * s2(c,r), no atomics ----
        {
            int nw = Cn * TB;
#pragma unroll 2
            for (int p = tid; p < nw; p += NTHR) {
                int cl = p >> 5;
                int r  = p & 31;
                int c  = ck0 + cl;
                size_t rowoff = (size_t)(b0 + r) * DIM;

                float s1 = 0.0f;
                int e0 = sh_cp1[c], e1 = sh_cp1[c + 1];
                for (int e = e0; e < e1; e++) {
                    unsigned u = sh_e1[e];
                    float x = __ldg(&x1[rowoff + (u & 1023u)]);
                    s1 += (u & 0x8000u) ? -x : x;
                }
                float s2 = 0.0f;
                int f0 = sh_cp2[c], f1 = sh_cp2[c + 1];
                for (int e = f0; e < f1; e++) {
                    unsigned u = sh_e2[e];
                    float x = __ldg(&x2[rowoff + (u & 1023u)]);
                    s2 += (u & 0x8000u) ? -x : x;
                }
                s1c[cl * TB + r] = s1 * s2;
            }
        }
        __syncthreads();

        // ---- GEMM: acc += v[32 x Cn] @ Wc[Cn x 512] ----
        // warp-uniform W loads (broadcast), per-lane v from smem.
        const float* Wp = g_Wc + (size_t)ck0 * OUT + o0;
#pragma unroll 2
        for (int cl = 0; cl < Cn; cl++) {
            float v = s1c[cl * TB + lane];          // conflict-free LDS.32
            unsigned long long v2 = pack2(v, v);    // 1 MOV

            const ulonglong2* wq = (const ulonglong2*)(Wp + (size_t)cl * OUT);
            ulonglong2 w0 = __ldg(wq + 0);          // uniform -> 1 wavefront
            ulonglong2 w1 = __ldg(wq + 1);
            ulonglong2 w2 = __ldg(wq + 2);
            ulonglong2 w3 = __ldg(wq + 3);
            ulonglong2 w4 = __ldg(wq + 4);
            ulonglong2 w5 = __ldg(wq + 5);
            ulonglong2 w6 = __ldg(wq + 6);
            ulonglong2 w7 = __ldg(wq + 7);

            acc2[0]  = ffma2(v2, w0.x, acc2[0]);
            acc2[1]  = ffma2(v2, w0.y, acc2[1]);
            acc2[2]  = ffma2(v2, w1.x, acc2[2]);
            acc2[3]  = ffma2(v2, w1.y, acc2[3]);
            acc2[4]  = ffma2(v2, w2.x, acc2[4]);
            acc2[5]  = ffma2(v2, w2.y, acc2[5]);
            acc2[6]  = ffma2(v2, w3.x, acc2[6]);
            acc2[7]  = ffma2(v2, w3.y, acc2[7]);
            acc2[8]  = ffma2(v2, w4.x, acc2[8]);
            acc2[9]  = ffma2(v2, w4.y, acc2[9]);
            acc2[10] = ffma2(v2, w5.x, acc2[10]);
            acc2[11] = ffma2(v2, w5.y, acc2[11]);
            acc2[12] = ffma2(v2, w6.x, acc2[12]);
            acc2[13] = ffma2(v2, w6.y, acc2[13]);
            acc2[14] = ffma2(v2, w7.x, acc2[14]);
            acc2[15] = ffma2(v2, w7.y, acc2[15]);
        }
        __syncthreads();   // s1c rewritten next chunk
    }

    // -------- LayerNorm: reduce row `lane` across the 16 warps -------------
    {
        float s = 0.0f, q = 0.0f;
#pragma unroll
        for (int k = 0; k < 16; k++) {
            float lo, hi;
            unpack2(acc2[k], lo, hi);
            s += lo + hi;
            q += lo * lo + hi * hi;
        }
        red_s[lane * 17 + wrp] = s;     // padded: conflict-free
        red_q[lane * 17 + wrp] = q;
    }
    __syncthreads();
    if (tid < TB) {
        float s = 0.0f, q = 0.0f;
#pragma unroll
        for (int u = 0; u < 16; u++) {
            s += red_s[tid * 17 + u];
            q += red_q[tid * 17 + u];
        }
        float mu  = s * (1.0f / OUT);
        float var = q * (1.0f / OUT) - mu * mu;
        sh_mu[tid] = mu;
        sh_rs[tid] = rsqrtf(var + LN_EPS);
    }
    __syncthreads();

    // -------- normalize, affine, ReLU, store -------------------------------
    {
        float mu = sh_mu[lane];
        float rs = sh_rs[lane];
        float* dst = out + (size_t)(b0 + lane) * OUT + o0;
        const float* ga = gamma + o0;
        const float* be = beta + o0;
#pragma unroll
        for (int q = 0; q < 4; q++) {
            float4 g0 = *(const float4*)(ga + q * 8);
            float4 g1 = *(const float4*)(ga + q * 8 + 4);
            float4 e0 = *(const float4*)(be + q * 8);
            float4 e1 = *(const float4*)(be + q * 8 + 4);
            float gg[8] = {g0.x, g0.y, g0.z, g0.w, g1.x, g1.y, g1.z, g1.w};
            float ee[8] = {e0.x, e0.y, e0.z, e0.w, e1.x, e1.y, e1.z, e1.w};
            float o[8];
#pragma unroll
            for (int k = 0; k < 4; k++) {
                float lo, hi;
                unpack2(acc2[q * 4 + k], lo, hi);
                o[2 * k]     = fmaxf((lo - mu) * rs * gg[2 * k]     + ee[2 * k],     0.0f);
                o[2 * k + 1] = fmaxf((hi - mu) * rs * gg[2 * k + 1] + ee[2 * k + 1], 0.0f);
            }
            *(float4*)(dst + q * 8)     = make_float4(o[0], o[1], o[2], o[3]);
            *(float4*)(dst + q * 8 + 4) = make_float4(o[4], o[5], o[6], o[7]);
        }
    }
}

// ---------------------------------------------------------------------------
extern "C" void kernel_launch(void* const* d_in, const int* in_sizes, int n_in,
                              void* d_out, int out_size)
{
    const float* x1    = (const float*)d_in[0];
    const float* x2    = (const float*)d_in[1];
    const float* S1    = (const float*)d_in[2];
    const float* S2    = (const float*)d_in[3];
    const float* W     = (const float*)d_in[4];
    const float* b     = (const float*)d_in[5];
    const float* gamma = (const float*)d_in[6];
    const float* beta  = (const float*)d_in[7];
    float* out = (float*)d_out;

    k_extract<<<2 * DIM, 256>>>(S1, S2);
    k_build<<<1, 1024>>>();
    k_wgather<<<MCAP, OUT>>>(W);
    k_main<<<BATCH / TB, NTHR>>>(x1, x2, b, gamma, beta, out);
}

// round 7
// speedup vs baseline: 2.1892x; 1.5008x over previous
#include <cuda_runtime.h>
#include <cuda_bf16.h>
#include <math.h>

// Problem constants
#define BATCH   8192
#define DIM     1024      // DIM1 == DIM2
#define SKETCH  8192
#define OUT     512
#define LN_EPS  1e-5f

#define MCAP    1024      // |J| <= 1024
#define CCH     128       // column chunk for main kernel
#define TB      64        // batch rows per CTA in main kernel
#define NTHR    1024      // threads per CTA (32 warps)
#define SUBCL   8         // W staging sub-chunk (8 cols x 512 = 16KB)

// ---------------- device globals (scratch; no cudaMalloc allowed) ----------
__device__ unsigned int g_idx1[DIM];     // per input dim: (signbit<<31) | bucket
__device__ unsigned int g_idx2[DIM];
__device__ int          g_m;             // |J|
__device__ int          g_colJ[MCAP];    // compact c -> original column j
__device__ int          g_cp1[MCAP + 1]; // CSR col ptrs, side 1
__device__ int          g_cp2[MCAP + 1];
__device__ unsigned int g_ent1[MCAP];    // CSR entries: (sign<<15) | i
__device__ unsigned int g_ent2[MCAP];
__device__ float        g_Wc[MCAP * OUT]; // compacted W rows

// -------- f32x2 packed-FMA helpers (PTX-only; ptxas never emits these) -----
__device__ __forceinline__ unsigned long long pack2(float lo, float hi) {
    unsigned long long r;
    asm("mov.b64 %0, {%1, %2};" : "=l"(r) : "f"(lo), "f"(hi));
    return r;
}
__device__ __forceinline__ void unpack2(unsigned long long v, float& lo, float& hi) {
    asm("mov.b64 {%0, %1}, %2;" : "=f"(lo), "=f"(hi) : "l"(v));
}
__device__ __forceinline__ unsigned long long ffma2(unsigned long long a,
                                                    unsigned long long b,
                                                    unsigned long long c) {
    unsigned long long d;
    asm("fma.rn.f32x2 %0, %1, %2, %3;" : "=l"(d) : "l"(a), "l"(b), "l"(c));
    return d;
}

// ---------------------------------------------------------------------------
// Kernel A: find the single nonzero per row of S1/S2. Coalesced float4 scan.
// ---------------------------------------------------------------------------
__global__ void k_extract(const float* __restrict__ S1,
                          const float* __restrict__ S2)
{
    int row = blockIdx.x;
    const float* S;
    unsigned int* outp;
    if (row < DIM) { S = S1; outp = g_idx1; }
    else           { S = S2; outp = g_idx2; row -= DIM; }

    const float4* p = (const float4*)(S + (size_t)row * SKETCH);
    int t = threadIdx.x;
#pragma unroll
    for (int k = 0; k < SKETCH / 4 / 256; k++) {
        int v4 = t + k * 256;
        float4 v = p[v4];
        int base = v4 * 4;
        if (v.x != 0.0f) outp[row] = (unsigned)(base + 0) | (v.x < 0.0f ? 0x80000000u : 0u);
        if (v.y != 0.0f) outp[row] = (unsigned)(base + 1) | (v.y < 0.0f ? 0x80000000u : 0u);
        if (v.z != 0.0f) outp[row] = (unsigned)(base + 2) | (v.z < 0.0f ? 0x80000000u : 0u);
        if (v.w != 0.0f) outp[row] = (unsigned)(base + 3) | (v.w < 0.0f ? 0x80000000u : 0u);
    }
}

// ---------------------------------------------------------------------------
// Kernel B: build compact structure + per-column CSR. One CTA, 1024 threads.
// ---------------------------------------------------------------------------
__global__ void k_build()
{
    __shared__ int cnt[SKETCH];      // packed occupancy counts, then colmap
    __shared__ int scanbuf[1024];
    __shared__ int colcnt[MCAP];     // per-column entry counts / running offsets

    int t = threadIdx.x;

    for (int j = t; j < SKETCH; j += 1024) cnt[j] = 0;
    __syncthreads();

    unsigned u1 = g_idx1[t];
    unsigned u2 = g_idx2[t];
    atomicAdd(&cnt[u1 & (SKETCH - 1)], 1);
    atomicAdd(&cnt[u2 & (SKETCH - 1)], 1 << 16);
    __syncthreads();

    // qualification + prefix scan: thread t owns j in [t*8, t*8+8)
    int q = 0;
    int qual[8];
#pragma unroll
    for (int u = 0; u < 8; u++) {
        int j = t * 8 + u;
        int c = cnt[j];
        qual[u] = ((c & 0xFFFF) > 0 && (c >> 16) > 0) ? 1 : 0;
        q += qual[u];
    }
    scanbuf[t] = q;
    __syncthreads();
    for (int off = 1; off < 1024; off <<= 1) {
        int v = (t >= off) ? scanbuf[t - off] : 0;
        __syncthreads();
        scanbuf[t] += v;
        __syncthreads();
    }
    int excl = scanbuf[t] - q;
    int total = scanbuf[1023];

#pragma unroll
    for (int u = 0; u < 8; u++) {
        int j = t * 8 + u;
        if (qual[u]) { g_colJ[excl] = j; cnt[j] = excl; excl++; }
        else         { cnt[j] = -1; }
    }
    if (t == 0) g_m = total;
    __syncthreads();

    // CSR build for both sides
    int c1 = cnt[u1 & (SKETCH - 1)];
    int c2 = cnt[u2 & (SKETCH - 1)];
#pragma unroll
    for (int s = 0; s < 2; s++) {
        int cc = s ? c2 : c1;
        unsigned uu = s ? u2 : u1;
        int* cp = s ? g_cp2 : g_cp1;
        unsigned int* ent = s ? g_ent2 : g_ent1;

        colcnt[t] = 0;
        __syncthreads();
        if (cc >= 0) atomicAdd(&colcnt[cc], 1);
        __syncthreads();

        int myc = colcnt[t];
        scanbuf[t] = myc;
        __syncthreads();
        for (int off = 1; off < 1024; off <<= 1) {
            int v = (t >= off) ? scanbuf[t - off] : 0;
            __syncthreads();
            scanbuf[t] += v;
            __syncthreads();
        }
        int ex = scanbuf[t] - myc;
        cp[t] = ex;
        if (t == 1023) cp[1024] = scanbuf[1023];
        colcnt[t] = ex;      // running offsets
        __syncthreads();
        if (cc >= 0) {
            int slot = atomicAdd(&colcnt[cc], 1);
            ent[slot] = (((uu >> 31) & 1u) << 15) | (unsigned)t;
        }
        __syncthreads();
    }
}

// ---------------------------------------------------------------------------
// Kernel B2: gather compacted W rows.
// ---------------------------------------------------------------------------
__global__ void k_wgather(const float* __restrict__ W)
{
    int c = blockIdx.x;
    if (c < g_m) {
        g_Wc[(size_t)c * OUT + threadIdx.x] =
            W[(size_t)g_colJ[c] * OUT + threadIdx.x];
    }
}

// ---------------------------------------------------------------------------
// Main fused kernel. TB=64 rows/CTA, 1024 threads (32 warps), 128 CTAs
// (exactly one wave on 148 SMs).
//  GEMM mapping: warp = 16 output cols (32x16=512), lane = 2 rows
//  (rows 2*lane, 2*lane+1). W is staged gmem->smem in 8-col sub-tiles and
//  consumed via warp-uniform (broadcast) LDS.128; v comes as one LDS.64.
//  f32x2 packs two adjacent output columns.
//  Phase 1: CSR gather — v[c][r] = s1(c,r)*s2(c,r); cp/ent reads are
//  warp-uniform __ldg from L2 (c is constant across a warp).
//  Epilogue: LayerNorm (bias folded into acc init) + ReLU.
// ---------------------------------------------------------------------------
// one GEMM step for column `base+c2` of the current chunk
#define GEMM_STEP(c2_)                                                         \
    {                                                                          \
        float2 vv = *(const float2*)&s1c[(base + (c2_)) * TB + r0];            \
        unsigned long long v2a = pack2(vv.x, vv.x);                            \
        unsigned long long v2b = pack2(vv.y, vv.y);                            \
        const ulonglong2* wp = (const ulonglong2*)&WS[(c2_) * OUT + o0];       \
        ulonglong2 w01 = wp[0];                                                \
        ulonglong2 w23 = wp[1];                                                \
        ulonglong2 w45 = wp[2];                                                \
        ulonglong2 w67 = wp[3];                                                \
        acc2[0][0] = ffma2(v2a, w01.x, acc2[0][0]);                            \
        acc2[1][0] = ffma2(v2b, w01.x, acc2[1][0]);                            \
        acc2[0][1] = ffma2(v2a, w01.y, acc2[0][1]);                            \
        acc2[1][1] = ffma2(v2b, w01.y, acc2[1][1]);                            \
        acc2[0][2] = ffma2(v2a, w23.x, acc2[0][2]);                            \
        acc2[1][2] = ffma2(v2b, w23.x, acc2[1][2]);                            \
        acc2[0][3] = ffma2(v2a, w23.y, acc2[0][3]);                            \
        acc2[1][3] = ffma2(v2b, w23.y, acc2[1][3]);                            \
        acc2[0][4] = ffma2(v2a, w45.x, acc2[0][4]);                            \
        acc2[1][4] = ffma2(v2b, w45.x, acc2[1][4]);                            \
        acc2[0][5] = ffma2(v2a, w45.y, acc2[0][5]);                            \
        acc2[1][5] = ffma2(v2b, w45.y, acc2[1][5]);                            \
        acc2[0][6] = ffma2(v2a, w67.x, acc2[0][6]);                            \
        acc2[1][6] = ffma2(v2b, w67.x, acc2[1][6]);                            \
        acc2[0][7] = ffma2(v2a, w67.y, acc2[0][7]);                            \
        acc2[1][7] = ffma2(v2b, w67.y, acc2[1][7]);                            \
    }

__global__ void __launch_bounds__(NTHR, 1)
k_main(const float* __restrict__ x1, const float* __restrict__ x2,
       const float* __restrict__ bias, const float* __restrict__ gamma,
       const float* __restrict__ beta, float* __restrict__ out)
{
    __shared__ __align__(16) float s1c[CCH * TB];    // 32KB; LN bufs alias
    __shared__ __align__(16) float WS[SUBCL * OUT];  // 16KB; mu/rs alias

    int tid  = threadIdx.x;
    int lane = tid & 31;
    int wrp  = tid >> 5;          // 0..31 -> cols [wrp*16, wrp*16+16)
    int o0   = wrp * 16;
    int r0   = lane * 2;          // rows r0, r0+1
    int b0   = blockIdx.x * TB;

    int m = g_m;                  // L2 broadcast
    int nch = (m + CCH - 1) / CCH;

    // accumulators: acc2[p][k] = row (r0+p), cols (o0+2k, o0+2k+1)
    unsigned long long acc2[2][8];
    {
        const ulonglong2* bq = (const ulonglong2*)(bias + o0);
#pragma unroll
        for (int q = 0; q < 4; q++) {
            ulonglong2 bb = __ldg(bq + q);
            acc2[0][2 * q]     = bb.x;
            acc2[0][2 * q + 1] = bb.y;
            acc2[1][2 * q]     = bb.x;
            acc2[1][2 * q + 1] = bb.y;
        }
    }

    for (int ch = 0; ch < nch; ch++) {
        int ck0 = ch * CCH;
        int Cn  = min(CCH, m - ck0);

        // ---- gather: v[c][r] = s1(c,r) * s2(c,r) ----
        // c is warp-uniform (p>>6 constant across 32 consecutive p), so the
        // cp/ent loads are broadcast; only the x loads are scattered.
        {
            int nw = Cn * TB;
            for (int p = tid; p < nw; p += NTHR) {
                int cl = p >> 6;
                int r  = p & 63;
                int c  = ck0 + cl;
                size_t rowoff = (size_t)(b0 + r) * DIM;

                float s1 = 0.0f;
                int e0 = __ldg(&g_cp1[c]), e1 = __ldg(&g_cp1[c + 1]);
                for (int e = e0; e < e1; e++) {
                    unsigned u = __ldg(&g_ent1[e]);
                    float x = __ldg(&x1[rowoff + (u & 1023u)]);
                    s1 += (u & 0x8000u) ? -x : x;
                }
                float s2 = 0.0f;
                int f0 = __ldg(&g_cp2[c]), f1 = __ldg(&g_cp2[c + 1]);
                for (int e = f0; e < f1; e++) {
                    unsigned u = __ldg(&g_ent2[e]);
                    float x = __ldg(&x2[rowoff + (u & 1023u)]);
                    s2 += (u & 0x8000u) ? -x : x;
                }
                s1c[cl * TB + r] = s1 * s2;
            }
        }
        __syncthreads();

        // ---- GEMM over sub-chunks: stage 8 W cols to smem, then FFMA2 ----
        int nsub = (Cn + SUBCL - 1) / SUBCL;
        for (int sub = 0; sub < nsub; sub++) {
            // stage W: 8 x 512 floats = 1 float4 per thread, coalesced
            {
                int row = tid >> 7;          // 0..7
                int col = (tid & 127) * 4;
                *(float4*)&WS[row * OUT + col] = __ldg(
                    (const float4*)&g_Wc[(size_t)(ck0 + sub * SUBCL + row) * OUT + col]);
            }
            __syncthreads();

            int base = sub * SUBCL;
            int Csub = min(SUBCL, Cn - base);
            if (Csub == SUBCL) {
#pragma unroll
                for (int c2 = 0; c2 < SUBCL; c2++) GEMM_STEP(c2)
            } else {
                for (int c2 = 0; c2 < Csub; c2++) GEMM_STEP(c2)
            }
            __syncthreads();   // WS (and, on last sub, s1c) about to be reused
        }
    }

    // -------- LayerNorm: reduce each row across the 32 warps ---------------
    float* red_s = s1c;                  // [64][33], aliases product tile
    float* red_q = s1c + TB * 33;
#pragma unroll
    for (int p = 0; p < 2; p++) {
        float s = 0.0f, q = 0.0f;
#pragma unroll
        for (int k = 0; k < 8; k++) {
            float lo, hi;
            unpack2(acc2[p][k], lo, hi);
            s += lo + hi;
            q += lo * lo + hi * hi;
        }
        red_s[(r0 + p) * 33 + wrp] = s;
        red_q[(r0 + p) * 33 + wrp] = q;
    }
    __syncthreads();

    float* shmu = WS;                    // aliases W staging buffer
    float* shrs = WS + TB;
    if (tid < TB) {
        float s = 0.0f, q = 0.0f;
#pragma unroll
        for (int w = 0; w < 32; w++) {
            s += red_s[tid * 33 + w];
            q += red_q[tid * 33 + w];
        }
        float mu  = s * (1.0f / OUT);
        float var = q * (1.0f / OUT) - mu * mu;
        shmu[tid] = mu;
        shrs[tid] = rsqrtf(var + LN_EPS);
    }
    __syncthreads();

    // -------- normalize, affine, ReLU, store -------------------------------
#pragma unroll
    for (int p = 0; p < 2; p++) {
        int row = r0 + p;
        float mu = shmu[row];
        float rs = shrs[row];
        float* dst = out + (size_t)(b0 + row) * OUT + o0;
#pragma unroll
        for (int q = 0; q < 4; q++) {
            float4 g4 = __ldg((const float4*)(gamma + o0 + 4 * q));
            float4 e4 = __ldg((const float4*)(beta  + o0 + 4 * q));
            float lo0, hi0, lo1, hi1;
            unpack2(acc2[p][2 * q],     lo0, hi0);
            unpack2(acc2[p][2 * q + 1], lo1, hi1);
            float4 o4;
            o4.x = fmaxf((lo0 - mu) * rs * g4.x + e4.x, 0.0f);
            o4.y = fmaxf((hi0 - mu) * rs * g4.y + e4.y, 0.0f);
            o4.z = fmaxf((lo1 - mu) * rs * g4.z + e4.z, 0.0f);
            o4.w = fmaxf((hi1 - mu) * rs * g4.w + e4.w, 0.0f);
            *(float4*)(dst + 4 * q) = o4;
        }
    }
}

// ---------------------------------------------------------------------------
extern "C" void kernel_launch(void* const* d_in, const int* in_sizes, int n_in,
                              void* d_out, int out_size)
{
    const float* x1    = (const float*)d_in[0];
    const float* x2    = (const float*)d_in[1];
    const float* S1    = (const float*)d_in[2];
    const float* S2    = (const float*)d_in[3];
    const float* W     = (const float*)d_in[4];
    const float* b     = (const float*)d_in[5];
    const float* gamma = (const float*)d_in[6];
    const float* beta  = (const float*)d_in[7];
    float* out = (float*)d_out;

    k_extract<<<2 * DIM, 256>>>(S1, S2);
    k_build<<<1, 1024>>>();
    k_wgather<<<MCAP, OUT>>>(W);
    k_main<<<BATCH / TB, NTHR>>>(x1, x2, b, gamma, beta, out);
}